// round 10
// baseline (speedup 1.0000x reference)
#include <cuda_runtime.h>
#include <math.h>

// Problem constants
#define Bn    8
#define Cdim  256
#define Nsp   16384         // 128*128
#define HEADS 8
#define Dd    32

// -------------------- device scratch (no allocations allowed) ---------------
__device__ float g_kv[Bn * Dd * Nsp];       // 16 MiB: kv = conv1x1_bn(x)
__device__ float g_rowmax[Bn * Dd];
__device__ float g_Z[Bn * Dd];
__device__ float g_ctx[Bn * Dd * Dd];       // raw (unnormalized) context
__device__ float g_ctxn[Bn * Dd * Dd];      // normalized context

// -------------------- f32x2 packed-FMA helpers (sm_103a) --------------------
__device__ __forceinline__ unsigned long long pk2(float x, float y) {
    unsigned long long r;
    asm("mov.b64 %0, {%1, %2};" : "=l"(r) : "f"(x), "f"(y));
    return r;
}
__device__ __forceinline__ void upk2(unsigned long long v, float& x, float& y) {
    asm("mov.b64 {%0, %1}, %2;" : "=f"(x), "=f"(y) : "l"(v));
}
__device__ __forceinline__ void fma2(unsigned long long& d,
                                     unsigned long long a, unsigned long long b) {
    asm("fma.rn.f32x2 %0, %1, %2, %0;" : "+l"(d) : "l"(a), "l"(b));
}

// ======================= kernel A: kv = wkv@x * s + b =======================
__global__ void kv_kernel(const float* __restrict__ x, const float* __restrict__ wkv,
                          const float* __restrict__ kvs, const float* __restrict__ kvb)
{
    __shared__ float w_s[Dd * Cdim];                 // 32 KB
    const int b = blockIdx.y;
    const int t = threadIdx.x;
    const int n = blockIdx.x * 256 + t;

    for (int i = t; i < Dd * Cdim / 4; i += 256)
        ((float4*)w_s)[i] = ((const float4*)wkv)[i];
    __syncthreads();

    const float* xp = x + (size_t)b * Cdim * Nsp + n;
    float acc[Dd];
#pragma unroll
    for (int d = 0; d < Dd; d++) acc[d] = 0.f;

#pragma unroll 1
    for (int c = 0; c < Cdim; c += 4) {
        float x0 = xp[(size_t)(c + 0) * Nsp];
        float x1 = xp[(size_t)(c + 1) * Nsp];
        float x2 = xp[(size_t)(c + 2) * Nsp];
        float x3 = xp[(size_t)(c + 3) * Nsp];
#pragma unroll
        for (int d = 0; d < Dd; d++) {
            float4 w = *(const float4*)&w_s[d * Cdim + c];
            acc[d] += w.x * x0 + w.y * x1 + w.z * x2 + w.w * x3;
        }
    }

    float* kvp = g_kv + (size_t)b * Dd * Nsp + n;
#pragma unroll
    for (int d = 0; d < Dd; d++)
        kvp[(size_t)d * Nsp] = acc[d] * kvs[d] + kvb[d];
}

// ======================= kernel B: per-(b,d) row max over N =================
__global__ void rowmax_kernel()
{
    const int row = blockIdx.x;                      // b*32 + d
    const float* p = g_kv + (size_t)row * Nsp;
    float m = -1e30f;
    for (int i = threadIdx.x; i < Nsp; i += 256) m = fmaxf(m, p[i]);
    __shared__ float sm[8];
    for (int o = 16; o > 0; o >>= 1) m = fmaxf(m, __shfl_down_sync(0xffffffffu, m, o));
    if ((threadIdx.x & 31) == 0) sm[threadIdx.x >> 5] = m;
    __syncthreads();
    if (threadIdx.x == 0) {
        float mm = sm[0];
#pragma unroll
        for (int i = 1; i < 8; i++) mm = fmaxf(mm, sm[i]);
        g_rowmax[row] = mm;
    }
}

// ======================= zero ctx/Z accumulators =============================
__global__ void zero_kernel()
{
    int i = blockIdx.x * 256 + threadIdx.x;
    if (i < Bn * Dd * Dd) g_ctx[i] = 0.f;
    if (i < Bn * Dd)      g_Z[i]   = 0.f;
}

// ======================= kernel C: context partial sums ======================
#define CH  256
#define CHP 257   // +1 float pad: kills bank conflicts on column access
__global__ void ctx_kernel()
{
    extern __shared__ float sh[];
    float* Ks = sh;                  // [32][CHP] raw kv chunk
    float* Ws = sh + Dd * CHP;       // [32][CHP] exp weights
    const int b  = blockIdx.y;
    const int t  = threadIdx.x;
    const int n0 = blockIdx.x * CH;
    const float* kvp = g_kv + (size_t)b * Dd * Nsp + n0;

#pragma unroll
    for (int it = 0; it < 8; it++) {
        int f  = it * 256 + t;       // float4 index, 2048 total
        int d  = f >> 6;             // / (CH/4)
        int n4 = f & 63;
        float4 v = *(const float4*)(kvp + (size_t)d * Nsp + n4 * 4);
        Ks[d * CHP + n4 * 4 + 0] = v.x;
        Ks[d * CHP + n4 * 4 + 1] = v.y;
        Ks[d * CHP + n4 * 4 + 2] = v.z;
        Ks[d * CHP + n4 * 4 + 3] = v.w;
    }
    __syncthreads();

    {   // softmax numerator weights + partial Z
        int d  = t >> 3;
        int s0 = (t & 7) * 32;
        float mx = g_rowmax[b * Dd + d];
        float s = 0.f;
#pragma unroll
        for (int j = 0; j < 32; j++) {
            float w = __expf(Ks[d * CHP + s0 + j] - mx);
            Ws[d * CHP + s0 + j] = w;
            s += w;
        }
        s += __shfl_down_sync(0xffffffffu, s, 4);
        s += __shfl_down_sync(0xffffffffu, s, 2);
        s += __shfl_down_sync(0xffffffffu, s, 1);
        if ((t & 7) == 0) atomicAdd(&g_Z[b * Dd + d], s);
    }
    __syncthreads();

    {   // partial context[d][e] += sum_n W[d][n] * K[e][n]
        int d  = t >> 3;
        int e0 = (t & 7) * 4;
        float a0 = 0.f, a1 = 0.f, a2 = 0.f, a3 = 0.f;
#pragma unroll 4
        for (int n = 0; n < CH; n++) {
            float w = Ws[d * CHP + n];
            a0 += w * Ks[(e0 + 0) * CHP + n];
            a1 += w * Ks[(e0 + 1) * CHP + n];
            a2 += w * Ks[(e0 + 2) * CHP + n];
            a3 += w * Ks[(e0 + 3) * CHP + n];
        }
        float* cp = &g_ctx[((size_t)b * Dd + d) * Dd + e0];
        atomicAdd(cp + 0, a0); atomicAdd(cp + 1, a1);
        atomicAdd(cp + 2, a2); atomicAdd(cp + 3, a3);
    }
}

// ======================= kernel D: normalize context ========================
__global__ void ctxnorm_kernel()
{
    int i = blockIdx.x * 256 + threadIdx.x;
    if (i < Bn * Dd * Dd) g_ctxn[i] = g_ctx[i] / g_Z[i / Dd];
}

// ======================= main fused kernel ===================================
#define TN 64
#define KT 16

// Streamed 256x256 (A, global, row-major) @ 256xTN (B, smem) -> 8x8/thread in f32x2.
__device__ __forceinline__ void gemm_tile(
    const float* __restrict__ A, const float* __restrict__ Xs, float* __restrict__ As,
    int t, int tr, int tc, unsigned long long C2[8][4])
{
#pragma unroll
    for (int i = 0; i < 8; i++)
#pragma unroll
        for (int j = 0; j < 4; j++) C2[i][j] = 0ull;

    {   // preload k-tile 0 transposed: As[0][k][m] = A[m][k]
        const float4* ap = (const float4*)(A + (size_t)t * 256);
        float4 r0 = ap[0], r1 = ap[1], r2 = ap[2], r3 = ap[3];
        As[ 0*256 + t] = r0.x; As[ 1*256 + t] = r0.y; As[ 2*256 + t] = r0.z; As[ 3*256 + t] = r0.w;
        As[ 4*256 + t] = r1.x; As[ 5*256 + t] = r1.y; As[ 6*256 + t] = r1.z; As[ 7*256 + t] = r1.w;
        As[ 8*256 + t] = r2.x; As[ 9*256 + t] = r2.y; As[10*256 + t] = r2.z; As[11*256 + t] = r2.w;
        As[12*256 + t] = r3.x; As[13*256 + t] = r3.y; As[14*256 + t] = r3.z; As[15*256 + t] = r3.w;
    }
    __syncthreads();

#pragma unroll 1
    for (int kt = 0; kt < 16; kt++) {
        float4 p0, p1, p2, p3;
        if (kt < 15) {   // prefetch next A tile into registers
            const float4* ap = (const float4*)(A + (size_t)t * 256 + (kt + 1) * KT);
            p0 = ap[0]; p1 = ap[1]; p2 = ap[2]; p3 = ap[3];
        }
        const float* Ac = As + (kt & 1) * (KT * 256);
        const float* Bc = Xs + kt * (KT * TN);
#pragma unroll
        for (int k = 0; k < KT; k++) {
            float4 a0 = *(const float4*)(Ac + k * 256 + tr * 8);
            float4 a1 = *(const float4*)(Ac + k * 256 + tr * 8 + 4);
            float4 b0 = *(const float4*)(Bc + k * TN + tc * 8);
            float4 b1 = *(const float4*)(Bc + k * TN + tc * 8 + 4);
            unsigned long long bb0 = pk2(b0.x, b0.y);
            unsigned long long bb1 = pk2(b0.z, b0.w);
            unsigned long long bb2 = pk2(b1.x, b1.y);
            unsigned long long bb3 = pk2(b1.z, b1.w);
            float av[8] = {a0.x, a0.y, a0.z, a0.w, a1.x, a1.y, a1.z, a1.w};
#pragma unroll
            for (int i = 0; i < 8; i++) {
                unsigned long long aa = pk2(av[i], av[i]);
                fma2(C2[i][0], aa, bb0);
                fma2(C2[i][1], aa, bb1);
                fma2(C2[i][2], aa, bb2);
                fma2(C2[i][3], aa, bb3);
            }
        }
        if (kt < 15) {
            float* dst = As + ((kt + 1) & 1) * (KT * 256);
            dst[ 0*256 + t] = p0.x; dst[ 1*256 + t] = p0.y; dst[ 2*256 + t] = p0.z; dst[ 3*256 + t] = p0.w;
            dst[ 4*256 + t] = p1.x; dst[ 5*256 + t] = p1.y; dst[ 6*256 + t] = p1.z; dst[ 7*256 + t] = p1.w;
            dst[ 8*256 + t] = p2.x; dst[ 9*256 + t] = p2.y; dst[10*256 + t] = p2.z; dst[11*256 + t] = p2.w;
            dst[12*256 + t] = p3.x; dst[13*256 + t] = p3.y; dst[14*256 + t] = p3.z; dst[15*256 + t] = p3.w;
            __syncthreads();
        }
    }
    __syncthreads();
}

__global__ void __launch_bounds__(256, 2)
main_kernel(const float* __restrict__ x,
            const float* __restrict__ wq, const float* __restrict__ qsc, const float* __restrict__ qbi,
            const float* __restrict__ wp, const float* __restrict__ psc, const float* __restrict__ pbi,
            float* __restrict__ out)
{
    extern __shared__ float sh[];
    float* Xs = sh;                        // [256][64] : x -> qsm -> att -> out
    float* As = sh + 256 * TN;             // [2][16][256] streamed weight tiles
    float* Cx = sh + 256 * TN + 2 * KT * 256;  // [32][32] normalized context

    const int b  = blockIdx.y;
    const int n0 = blockIdx.x * TN;
    const int t  = threadIdx.x;
    const int tc = t & 7;
    const int tr = t >> 3;

    {   // coalesced float4 load of x tile [256][64]
        const float4* xp = (const float4*)(x + (size_t)b * Cdim * Nsp + n0);
#pragma unroll
        for (int it = 0; it < 16; it++) {
            int f  = it * 256 + t;     // 0..4095 ; row = f/16, col4 = f%16
            int c  = f >> 4;
            int n4 = f & 15;
            ((float4*)Xs)[f] = xp[(size_t)c * (Nsp / 4) + n4];
        }
    }
    ((float4*)Cx)[t & 255] = ((const float4*)(g_ctxn + (size_t)b * Dd * Dd))[t];
    __syncthreads();

    unsigned long long C2[8][4];

    // ---- GEMM1: q = wq @ x ----
    gemm_tile(wq, Xs, As, t, tr, tc, C2);

    // q affine -> Xs (overwrites x tile)
#pragma unroll
    for (int i = 0; i < 8; i++) {
        int m = tr * 8 + i;
        float s = __ldg(qsc + m), bia = __ldg(qbi + m);
#pragma unroll
        for (int j = 0; j < 4; j++) {
            float f0, f1; upk2(C2[i][j], f0, f1);
            Xs[m * TN + tc * 8 + 2 * j]     = f0 * s + bia;
            Xs[m * TN + tc * 8 + 2 * j + 1] = f1 * s + bia;
        }
    }
    __syncthreads();

    // ---- softmax over D per (head, column) ----
#pragma unroll
    for (int gg = 0; gg < 2; gg++) {
        int g   = t + gg * 256;     // 512 groups = 8 heads x 64 cols
        int col = g & 63;
        int h   = g >> 6;
        float* base = Xs + (h * Dd) * TN + col;
        float mx = base[0];
#pragma unroll
        for (int d = 1; d < Dd; d++) mx = fmaxf(mx, base[d * TN]);
        float ev[Dd];
        float sum = 0.f;
#pragma unroll
        for (int d = 0; d < Dd; d++) { ev[d] = __expf(base[d * TN] - mx); sum += ev[d]; }
        float inv = 1.f / sum;
#pragma unroll
        for (int d = 0; d < Dd; d++) base[d * TN] = ev[d] * inv;
    }
    __syncthreads();

    // ---- attended = ctx^T @ qsm per head, then ReLU, back into Xs ----
    float Areg[8][8];
#pragma unroll
    for (int i = 0; i < 8; i++)
#pragma unroll
        for (int j = 0; j < 8; j++) Areg[i][j] = 0.f;
    {
        int h  = tr >> 2;            // rows tr*8..tr*8+7 all live in head h
        int e0 = (tr & 3) * 8;       // h*32+e0 == tr*8
#pragma unroll
        for (int d = 0; d < Dd; d++) {
            const float* qrow = Xs + (h * Dd + d) * TN + tc * 8;
            float4 q0 = *(const float4*)qrow;
            float4 q1 = *(const float4*)(qrow + 4);
            const float* crow = Cx + d * Dd + e0;
            float4 c0 = *(const float4*)crow;
            float4 c1 = *(const float4*)(crow + 4);
            float qv[8] = {q0.x, q0.y, q0.z, q0.w, q1.x, q1.y, q1.z, q1.w};
            float cv[8] = {c0.x, c0.y, c0.z, c0.w, c1.x, c1.y, c1.z, c1.w};
#pragma unroll
            for (int i = 0; i < 8; i++)
#pragma unroll
                for (int j = 0; j < 8; j++) Areg[i][j] += cv[i] * qv[j];
        }
    }
    __syncthreads();
#pragma unroll
    for (int i = 0; i < 8; i++)
#pragma unroll
        for (int j = 0; j < 8; j++)
            Xs[(tr * 8 + i) * TN + tc * 8 + j] = fmaxf(Areg[i][j], 0.f);
    __syncthreads();

    // ---- GEMM2: out = wp @ relu(att) ----
    gemm_tile(wp, Xs, As, t, tr, tc, C2);

    // p affine -> Xs, then coalesced store
#pragma unroll
    for (int i = 0; i < 8; i++) {
        int m = tr * 8 + i;
        float s = __ldg(psc + m), bia = __ldg(pbi + m);
#pragma unroll
        for (int j = 0; j < 4; j++) {
            float f0, f1; upk2(C2[i][j], f0, f1);
            Xs[m * TN + tc * 8 + 2 * j]     = f0 * s + bia;
            Xs[m * TN + tc * 8 + 2 * j + 1] = f1 * s + bia;
        }
    }
    __syncthreads();
    {
        float4* op = (float4*)(out + (size_t)b * Cdim * Nsp + n0);
#pragma unroll
        for (int it = 0; it < 16; it++) {
            int f  = it * 256 + t;
            int c  = f >> 4;
            int n4 = f & 15;
            op[(size_t)c * (Nsp / 4) + n4] = ((float4*)Xs)[f];
        }
    }
}

// ======================= launch =============================================
extern "C" void kernel_launch(void* const* d_in, const int* in_sizes, int n_in,
                              void* d_out, int out_size)
{
    const float* x   = (const float*)d_in[0];
    const float* wq  = (const float*)d_in[1];
    const float* qsc = (const float*)d_in[2];
    const float* qbi = (const float*)d_in[3];
    const float* wkv = (const float*)d_in[4];
    const float* kvs = (const float*)d_in[5];
    const float* kvb = (const float*)d_in[6];
    const float* wp  = (const float*)d_in[7];
    const float* psc = (const float*)d_in[8];
    const float* pbi = (const float*)d_in[9];
    float* out = (float*)d_out;

    const int CTX_SMEM  = 2 * Dd * CHP * (int)sizeof(float);                 // 65792
    const int MAIN_SMEM = (256 * TN + 2 * KT * 256 + Dd * Dd) * (int)sizeof(float); // 102400

    cudaFuncSetAttribute(ctx_kernel,  cudaFuncAttributeMaxDynamicSharedMemorySize, CTX_SMEM);
    cudaFuncSetAttribute(main_kernel, cudaFuncAttributeMaxDynamicSharedMemorySize, MAIN_SMEM);

    kv_kernel<<<dim3(Nsp / 256, Bn), 256>>>(x, wkv, kvs, kvb);
    rowmax_kernel<<<Bn * Dd, 256>>>();
    zero_kernel<<<(Bn * Dd * Dd + 255) / 256, 256>>>();
    ctx_kernel<<<dim3(Nsp / CH, Bn), 256, CTX_SMEM>>>();
    ctxnorm_kernel<<<(Bn * Dd * Dd + 255) / 256, 256>>>();
    main_kernel<<<dim3(Nsp / TN, Bn), 256, MAIN_SMEM>>>(x, wq, qsc, qbi, wp, psc, pbi, out);
}

// round 11
// speedup vs baseline: 1.0017x; 1.0017x over previous
#include <cuda_runtime.h>
#include <math.h>

// Problem constants
#define Bn    8
#define Cdim  256
#define Nsp   16384         // 128*128
#define HEADS 8
#define Dd    32

// -------------------- device scratch (no allocations allowed) ---------------
__device__ float g_kv[Bn * Dd * Nsp];       // 16 MiB: kv = conv1x1_bn(x)
__device__ float g_rowmax[Bn * Dd];
__device__ float g_Z[Bn * Dd];
__device__ float g_ctx[Bn * Dd * Dd];       // raw (unnormalized) context
__device__ float g_ctxn[Bn * Dd * Dd];      // normalized context

// -------------------- f32x2 packed-FMA helpers (sm_103a) --------------------
__device__ __forceinline__ unsigned long long pk2(float x, float y) {
    unsigned long long r;
    asm("mov.b64 %0, {%1, %2};" : "=l"(r) : "f"(x), "f"(y));
    return r;
}
__device__ __forceinline__ void upk2(unsigned long long v, float& x, float& y) {
    asm("mov.b64 {%0, %1}, %2;" : "=f"(x), "=f"(y) : "l"(v));
}
__device__ __forceinline__ void fma2(unsigned long long& d,
                                     unsigned long long a, unsigned long long b) {
    asm("fma.rn.f32x2 %0, %1, %2, %0;" : "+l"(d) : "l"(a), "l"(b));
}

// ======================= kernel A: kv = wkv@x * s + b =======================
__global__ void kv_kernel(const float* __restrict__ x, const float* __restrict__ wkv,
                          const float* __restrict__ kvs, const float* __restrict__ kvb)
{
    __shared__ float w_s[Dd * Cdim];                 // 32 KB
    const int b = blockIdx.y;
    const int t = threadIdx.x;
    const int n = blockIdx.x * 256 + t;

    for (int i = t; i < Dd * Cdim / 4; i += 256)
        ((float4*)w_s)[i] = ((const float4*)wkv)[i];
    __syncthreads();

    const float* xp = x + (size_t)b * Cdim * Nsp + n;
    float acc[Dd];
#pragma unroll
    for (int d = 0; d < Dd; d++) acc[d] = 0.f;

#pragma unroll 1
    for (int c = 0; c < Cdim; c += 4) {
        float x0 = xp[(size_t)(c + 0) * Nsp];
        float x1 = xp[(size_t)(c + 1) * Nsp];
        float x2 = xp[(size_t)(c + 2) * Nsp];
        float x3 = xp[(size_t)(c + 3) * Nsp];
#pragma unroll
        for (int d = 0; d < Dd; d++) {
            float4 w = *(const float4*)&w_s[d * Cdim + c];
            acc[d] += w.x * x0 + w.y * x1 + w.z * x2 + w.w * x3;
        }
    }

    float* kvp = g_kv + (size_t)b * Dd * Nsp + n;
#pragma unroll
    for (int d = 0; d < Dd; d++)
        kvp[(size_t)d * Nsp] = acc[d] * kvs[d] + kvb[d];
}

// ======================= kernel B: per-(b,d) row max over N =================
__global__ void rowmax_kernel()
{
    const int row = blockIdx.x;                      // b*32 + d
    const float* p = g_kv + (size_t)row * Nsp;
    float m = -1e30f;
    for (int i = threadIdx.x; i < Nsp; i += 256) m = fmaxf(m, p[i]);
    __shared__ float sm[8];
    for (int o = 16; o > 0; o >>= 1) m = fmaxf(m, __shfl_down_sync(0xffffffffu, m, o));
    if ((threadIdx.x & 31) == 0) sm[threadIdx.x >> 5] = m;
    __syncthreads();
    if (threadIdx.x == 0) {
        float mm = sm[0];
#pragma unroll
        for (int i = 1; i < 8; i++) mm = fmaxf(mm, sm[i]);
        g_rowmax[row] = mm;
    }
}

// ======================= zero ctx/Z accumulators =============================
__global__ void zero_kernel()
{
    int i = blockIdx.x * 256 + threadIdx.x;
    if (i < Bn * Dd * Dd) g_ctx[i] = 0.f;
    if (i < Bn * Dd)      g_Z[i]   = 0.f;
}

// ======================= kernel C: context partial sums ======================
#define CH  256
#define CHP 257   // +1 float pad: kills bank conflicts on column access
__global__ void ctx_kernel()
{
    extern __shared__ float sh[];
    float* Ks = sh;                  // [32][CHP] raw kv chunk
    float* Ws = sh + Dd * CHP;       // [32][CHP] exp weights
    const int b  = blockIdx.y;
    const int t  = threadIdx.x;
    const int n0 = blockIdx.x * CH;
    const float* kvp = g_kv + (size_t)b * Dd * Nsp + n0;

#pragma unroll
    for (int it = 0; it < 8; it++) {
        int f  = it * 256 + t;       // float4 index, 2048 total
        int d  = f >> 6;             // / (CH/4)
        int n4 = f & 63;
        float4 v = *(const float4*)(kvp + (size_t)d * Nsp + n4 * 4);
        Ks[d * CHP + n4 * 4 + 0] = v.x;
        Ks[d * CHP + n4 * 4 + 1] = v.y;
        Ks[d * CHP + n4 * 4 + 2] = v.z;
        Ks[d * CHP + n4 * 4 + 3] = v.w;
    }
    __syncthreads();

    {   // softmax numerator weights + partial Z
        int d  = t >> 3;
        int s0 = (t & 7) * 32;
        float mx = g_rowmax[b * Dd + d];
        float s = 0.f;
#pragma unroll
        for (int j = 0; j < 32; j++) {
            float w = __expf(Ks[d * CHP + s0 + j] - mx);
            Ws[d * CHP + s0 + j] = w;
            s += w;
        }
        s += __shfl_down_sync(0xffffffffu, s, 4);
        s += __shfl_down_sync(0xffffffffu, s, 2);
        s += __shfl_down_sync(0xffffffffu, s, 1);
        if ((t & 7) == 0) atomicAdd(&g_Z[b * Dd + d], s);
    }
    __syncthreads();

    {   // partial context[d][e] += sum_n W[d][n] * K[e][n]
        int d  = t >> 3;
        int e0 = (t & 7) * 4;
        float a0 = 0.f, a1 = 0.f, a2 = 0.f, a3 = 0.f;
#pragma unroll 4
        for (int n = 0; n < CH; n++) {
            float w = Ws[d * CHP + n];
            a0 += w * Ks[(e0 + 0) * CHP + n];
            a1 += w * Ks[(e0 + 1) * CHP + n];
            a2 += w * Ks[(e0 + 2) * CHP + n];
            a3 += w * Ks[(e0 + 3) * CHP + n];
        }
        float* cp = &g_ctx[((size_t)b * Dd + d) * Dd + e0];
        atomicAdd(cp + 0, a0); atomicAdd(cp + 1, a1);
        atomicAdd(cp + 2, a2); atomicAdd(cp + 3, a3);
    }
}

// ======================= kernel D: normalize context ========================
__global__ void ctxnorm_kernel()
{
    int i = blockIdx.x * 256 + threadIdx.x;
    if (i < Bn * Dd * Dd) g_ctxn[i] = g_ctx[i] / g_Z[i / Dd];
}

// ======================= main fused kernel ===================================
#define TN 64
#define KT 16

// Streamed 256x256 (A, global, row-major) @ 256xTN (B, smem) -> 8x8/thread in f32x2.
__device__ __forceinline__ void gemm_tile(
    const float* __restrict__ A, const float* __restrict__ Xs, float* __restrict__ As,
    int t, int tr, int tc, unsigned long long C2[8][4])
{
#pragma unroll
    for (int i = 0; i < 8; i++)
#pragma unroll
        for (int j = 0; j < 4; j++) C2[i][j] = 0ull;

    {   // preload k-tile 0 transposed: As[0][k][m] = A[m][k]
        const float4* ap = (const float4*)(A + (size_t)t * 256);
        float4 r0 = ap[0], r1 = ap[1], r2 = ap[2], r3 = ap[3];
        As[ 0*256 + t] = r0.x; As[ 1*256 + t] = r0.y; As[ 2*256 + t] = r0.z; As[ 3*256 + t] = r0.w;
        As[ 4*256 + t] = r1.x; As[ 5*256 + t] = r1.y; As[ 6*256 + t] = r1.z; As[ 7*256 + t] = r1.w;
        As[ 8*256 + t] = r2.x; As[ 9*256 + t] = r2.y; As[10*256 + t] = r2.z; As[11*256 + t] = r2.w;
        As[12*256 + t] = r3.x; As[13*256 + t] = r3.y; As[14*256 + t] = r3.z; As[15*256 + t] = r3.w;
    }
    __syncthreads();

#pragma unroll 1
    for (int kt = 0; kt < 16; kt++) {
        float4 p0, p1, p2, p3;
        if (kt < 15) {   // prefetch next A tile into registers
            const float4* ap = (const float4*)(A + (size_t)t * 256 + (kt + 1) * KT);
            p0 = ap[0]; p1 = ap[1]; p2 = ap[2]; p3 = ap[3];
        }
        const float* Ac = As + (kt & 1) * (KT * 256);
        const float* Bc = Xs + kt * (KT * TN);
#pragma unroll
        for (int k = 0; k < KT; k++) {
            float4 a0 = *(const float4*)(Ac + k * 256 + tr * 8);
            float4 a1 = *(const float4*)(Ac + k * 256 + tr * 8 + 4);
            float4 b0 = *(const float4*)(Bc + k * TN + tc * 8);
            float4 b1 = *(const float4*)(Bc + k * TN + tc * 8 + 4);
            unsigned long long bb0 = pk2(b0.x, b0.y);
            unsigned long long bb1 = pk2(b0.z, b0.w);
            unsigned long long bb2 = pk2(b1.x, b1.y);
            unsigned long long bb3 = pk2(b1.z, b1.w);
            float av[8] = {a0.x, a0.y, a0.z, a0.w, a1.x, a1.y, a1.z, a1.w};
#pragma unroll
            for (int i = 0; i < 8; i++) {
                unsigned long long aa = pk2(av[i], av[i]);
                fma2(C2[i][0], aa, bb0);
                fma2(C2[i][1], aa, bb1);
                fma2(C2[i][2], aa, bb2);
                fma2(C2[i][3], aa, bb3);
            }
        }
        if (kt < 15) {
            float* dst = As + ((kt + 1) & 1) * (KT * 256);
            dst[ 0*256 + t] = p0.x; dst[ 1*256 + t] = p0.y; dst[ 2*256 + t] = p0.z; dst[ 3*256 + t] = p0.w;
            dst[ 4*256 + t] = p1.x; dst[ 5*256 + t] = p1.y; dst[ 6*256 + t] = p1.z; dst[ 7*256 + t] = p1.w;
            dst[ 8*256 + t] = p2.x; dst[ 9*256 + t] = p2.y; dst[10*256 + t] = p2.z; dst[11*256 + t] = p2.w;
            dst[12*256 + t] = p3.x; dst[13*256 + t] = p3.y; dst[14*256 + t] = p3.z; dst[15*256 + t] = p3.w;
            __syncthreads();
        }
    }
    __syncthreads();
}

__global__ void __launch_bounds__(256, 2)
main_kernel(const float* __restrict__ x,
            const float* __restrict__ wq, const float* __restrict__ qsc, const float* __restrict__ qbi,
            const float* __restrict__ wp, const float* __restrict__ psc, const float* __restrict__ pbi,
            float* __restrict__ out)
{
    extern __shared__ float sh[];
    float* Xs = sh;                        // [256][64] : x -> qsm -> att -> out
    float* As = sh + 256 * TN;             // [2][16][256] streamed weight tiles
    float* Cx = sh + 256 * TN + 2 * KT * 256;  // [32][32] normalized context

    const int b  = blockIdx.y;
    const int n0 = blockIdx.x * TN;
    const int t  = threadIdx.x;
    const int tc = t & 7;
    const int tr = t >> 3;

    {   // coalesced float4 load of x tile [256][64]
        const float4* xp = (const float4*)(x + (size_t)b * Cdim * Nsp + n0);
#pragma unroll
        for (int it = 0; it < 16; it++) {
            int f  = it * 256 + t;     // 0..4095 ; row = f/16, col4 = f%16
            int c  = f >> 4;
            int n4 = f & 15;
            ((float4*)Xs)[f] = xp[(size_t)c * (Nsp / 4) + n4];
        }
    }
    ((float4*)Cx)[t & 255] = ((const float4*)(g_ctxn + (size_t)b * Dd * Dd))[t];
    __syncthreads();

    unsigned long long C2[8][4];

    // ---- GEMM1: q = wq @ x ----
    gemm_tile(wq, Xs, As, t, tr, tc, C2);

    // q affine -> Xs (overwrites x tile)
#pragma unroll
    for (int i = 0; i < 8; i++) {
        int m = tr * 8 + i;
        float s = __ldg(qsc + m), bia = __ldg(qbi + m);
#pragma unroll
        for (int j = 0; j < 4; j++) {
            float f0, f1; upk2(C2[i][j], f0, f1);
            Xs[m * TN + tc * 8 + 2 * j]     = f0 * s + bia;
            Xs[m * TN + tc * 8 + 2 * j + 1] = f1 * s + bia;
        }
    }
    __syncthreads();

    // ---- softmax over D per (head, column) ----
#pragma unroll
    for (int gg = 0; gg < 2; gg++) {
        int g   = t + gg * 256;     // 512 groups = 8 heads x 64 cols
        int col = g & 63;
        int h   = g >> 6;
        float* base = Xs + (h * Dd) * TN + col;
        float mx = base[0];
#pragma unroll
        for (int d = 1; d < Dd; d++) mx = fmaxf(mx, base[d * TN]);
        float ev[Dd];
        float sum = 0.f;
#pragma unroll
        for (int d = 0; d < Dd; d++) { ev[d] = __expf(base[d * TN] - mx); sum += ev[d]; }
        float inv = 1.f / sum;
#pragma unroll
        for (int d = 0; d < Dd; d++) base[d * TN] = ev[d] * inv;
    }
    __syncthreads();

    // ---- attended = ctx^T @ qsm per head, then ReLU, back into Xs ----
    float Areg[8][8];
#pragma unroll
    for (int i = 0; i < 8; i++)
#pragma unroll
        for (int j = 0; j < 8; j++) Areg[i][j] = 0.f;
    {
        int h  = tr >> 2;            // rows tr*8..tr*8+7 all live in head h
        int e0 = (tr & 3) * 8;       // h*32+e0 == tr*8
#pragma unroll
        for (int d = 0; d < Dd; d++) {
            const float* qrow = Xs + (h * Dd + d) * TN + tc * 8;
            float4 q0 = *(const float4*)qrow;
            float4 q1 = *(const float4*)(qrow + 4);
            const float* crow = Cx + d * Dd + e0;
            float4 c0 = *(const float4*)crow;
            float4 c1 = *(const float4*)(crow + 4);
            float qv[8] = {q0.x, q0.y, q0.z, q0.w, q1.x, q1.y, q1.z, q1.w};
            float cv[8] = {c0.x, c0.y, c0.z, c0.w, c1.x, c1.y, c1.z, c1.w};
#pragma unroll
            for (int i = 0; i < 8; i++)
#pragma unroll
                for (int j = 0; j < 8; j++) Areg[i][j] += cv[i] * qv[j];
        }
    }
    __syncthreads();
#pragma unroll
    for (int i = 0; i < 8; i++)
#pragma unroll
        for (int j = 0; j < 8; j++)
            Xs[(tr * 8 + i) * TN + tc * 8 + j] = fmaxf(Areg[i][j], 0.f);
    __syncthreads();

    // ---- GEMM2: out = wp @ relu(att) ----
    gemm_tile(wp, Xs, As, t, tr, tc, C2);

    // p affine -> Xs, then coalesced store
#pragma unroll
    for (int i = 0; i < 8; i++) {
        int m = tr * 8 + i;
        float s = __ldg(psc + m), bia = __ldg(pbi + m);
#pragma unroll
        for (int j = 0; j < 4; j++) {
            float f0, f1; upk2(C2[i][j], f0, f1);
            Xs[m * TN + tc * 8 + 2 * j]     = f0 * s + bia;
            Xs[m * TN + tc * 8 + 2 * j + 1] = f1 * s + bia;
        }
    }
    __syncthreads();
    {
        float4* op = (float4*)(out + (size_t)b * Cdim * Nsp + n0);
#pragma unroll
        for (int it = 0; it < 16; it++) {
            int f  = it * 256 + t;
            int c  = f >> 4;
            int n4 = f & 15;
            op[(size_t)c * (Nsp / 4) + n4] = ((float4*)Xs)[f];
        }
    }
}

// ======================= launch =============================================
extern "C" void kernel_launch(void* const* d_in, const int* in_sizes, int n_in,
                              void* d_out, int out_size)
{
    const float* x   = (const float*)d_in[0];
    const float* wq  = (const float*)d_in[1];
    const float* qsc = (const float*)d_in[2];
    const float* qbi = (const float*)d_in[3];
    const float* wkv = (const float*)d_in[4];
    const float* kvs = (const float*)d_in[5];
    const float* kvb = (const float*)d_in[6];
    const float* wp  = (const float*)d_in[7];
    const float* psc = (const float*)d_in[8];
    const float* pbi = (const float*)d_in[9];
    float* out = (float*)d_out;

    const int CTX_SMEM  = 2 * Dd * CHP * (int)sizeof(float);                 // 65792
    const int MAIN_SMEM = (256 * TN + 2 * KT * 256 + Dd * Dd) * (int)sizeof(float); // 102400

    cudaFuncSetAttribute(ctx_kernel,  cudaFuncAttributeMaxDynamicSharedMemorySize, CTX_SMEM);
    cudaFuncSetAttribute(main_kernel, cudaFuncAttributeMaxDynamicSharedMemorySize, MAIN_SMEM);

    kv_kernel<<<dim3(Nsp / 256, Bn), 256>>>(x, wkv, kvs, kvb);
    rowmax_kernel<<<Bn * Dd, 256>>>();
    zero_kernel<<<(Bn * Dd * Dd + 255) / 256, 256>>>();
    ctx_kernel<<<dim3(Nsp / CH, Bn), 256, CTX_SMEM>>>();
    ctxnorm_kernel<<<(Bn * Dd * Dd + 255) / 256, 256>>>();
    main_kernel<<<dim3(Nsp / TN, Bn), 256, MAIN_SMEM>>>(x, wq, qsc, qbi, wp, psc, pbi, out);
}

// round 12
// speedup vs baseline: 1.0066x; 1.0048x over previous
#include <cuda_runtime.h>
#include <math.h>

// Problem constants
#define Bn    8
#define Cdim  256
#define Nsp   16384         // 128*128
#define HEADS 8
#define Dd    32

// -------------------- device scratch (no allocations allowed) ---------------
__device__ float g_kv[Bn * Dd * Nsp];       // 16 MiB: kv = conv1x1_bn(x)
__device__ float g_rowmax[Bn * Dd];
__device__ float g_Z[Bn * Dd];
__device__ float g_ctx[Bn * Dd * Dd];       // raw (unnormalized) context
__device__ float g_ctxn[Bn * Dd * Dd];      // normalized context

// -------------------- f32x2 packed-FMA helpers (sm_103a) --------------------
__device__ __forceinline__ unsigned long long pk2(float x, float y) {
    unsigned long long r;
    asm("mov.b64 %0, {%1, %2};" : "=l"(r) : "f"(x), "f"(y));
    return r;
}
__device__ __forceinline__ void upk2(unsigned long long v, float& x, float& y) {
    asm("mov.b64 {%0, %1}, %2;" : "=f"(x), "=f"(y) : "l"(v));
}
__device__ __forceinline__ void fma2(unsigned long long& d,
                                     unsigned long long a, unsigned long long b) {
    asm("fma.rn.f32x2 %0, %1, %2, %0;" : "+l"(d) : "l"(a), "l"(b));
}

// ======================= kernel A: kv = wkv@x * s + b =======================
__global__ void kv_kernel(const float* __restrict__ x, const float* __restrict__ wkv,
                          const float* __restrict__ kvs, const float* __restrict__ kvb)
{
    __shared__ float w_s[Dd * Cdim];                 // 32 KB
    const int b = blockIdx.y;
    const int t = threadIdx.x;
    const int n = blockIdx.x * 256 + t;

    for (int i = t; i < Dd * Cdim / 4; i += 256)
        ((float4*)w_s)[i] = ((const float4*)wkv)[i];
    __syncthreads();

    const float* xp = x + (size_t)b * Cdim * Nsp + n;
    float acc[Dd];
#pragma unroll
    for (int d = 0; d < Dd; d++) acc[d] = 0.f;

#pragma unroll 1
    for (int c = 0; c < Cdim; c += 4) {
        float x0 = xp[(size_t)(c + 0) * Nsp];
        float x1 = xp[(size_t)(c + 1) * Nsp];
        float x2 = xp[(size_t)(c + 2) * Nsp];
        float x3 = xp[(size_t)(c + 3) * Nsp];
#pragma unroll
        for (int d = 0; d < Dd; d++) {
            float4 w = *(const float4*)&w_s[d * Cdim + c];
            acc[d] += w.x * x0 + w.y * x1 + w.z * x2 + w.w * x3;
        }
    }

    float* kvp = g_kv + (size_t)b * Dd * Nsp + n;
#pragma unroll
    for (int d = 0; d < Dd; d++)
        kvp[(size_t)d * Nsp] = acc[d] * kvs[d] + kvb[d];
}

// ======================= kernel B: per-(b,d) row max over N =================
__global__ void rowmax_kernel()
{
    const int row = blockIdx.x;                      // b*32 + d
    const float* p = g_kv + (size_t)row * Nsp;
    float m = -1e30f;
    for (int i = threadIdx.x; i < Nsp; i += 256) m = fmaxf(m, p[i]);
    __shared__ float sm[8];
    for (int o = 16; o > 0; o >>= 1) m = fmaxf(m, __shfl_down_sync(0xffffffffu, m, o));
    if ((threadIdx.x & 31) == 0) sm[threadIdx.x >> 5] = m;
    __syncthreads();
    if (threadIdx.x == 0) {
        float mm = sm[0];
#pragma unroll
        for (int i = 1; i < 8; i++) mm = fmaxf(mm, sm[i]);
        g_rowmax[row] = mm;
    }
}

// ======================= zero ctx/Z accumulators =============================
__global__ void zero_kernel()
{
    int i = blockIdx.x * 256 + threadIdx.x;
    if (i < Bn * Dd * Dd) g_ctx[i] = 0.f;
    if (i < Bn * Dd)      g_Z[i]   = 0.f;
}

// ======================= kernel C: context partial sums ======================
#define CH  256
#define CHP 257   // +1 float pad: kills bank conflicts on column access
__global__ void ctx_kernel()
{
    extern __shared__ float sh[];
    float* Ks = sh;                  // [32][CHP] raw kv chunk
    float* Ws = sh + Dd * CHP;       // [32][CHP] exp weights
    const int b  = blockIdx.y;
    const int t  = threadIdx.x;
    const int n0 = blockIdx.x * CH;
    const float* kvp = g_kv + (size_t)b * Dd * Nsp + n0;

#pragma unroll
    for (int it = 0; it < 8; it++) {
        int f  = it * 256 + t;       // float4 index, 2048 total
        int d  = f >> 6;             // / (CH/4)
        int n4 = f & 63;
        float4 v = *(const float4*)(kvp + (size_t)d * Nsp + n4 * 4);
        Ks[d * CHP + n4 * 4 + 0] = v.x;
        Ks[d * CHP + n4 * 4 + 1] = v.y;
        Ks[d * CHP + n4 * 4 + 2] = v.z;
        Ks[d * CHP + n4 * 4 + 3] = v.w;
    }
    __syncthreads();

    {   // softmax numerator weights + partial Z
        int d  = t >> 3;
        int s0 = (t & 7) * 32;
        float mx = g_rowmax[b * Dd + d];
        float s = 0.f;
#pragma unroll
        for (int j = 0; j < 32; j++) {
            float w = __expf(Ks[d * CHP + s0 + j] - mx);
            Ws[d * CHP + s0 + j] = w;
            s += w;
        }
        s += __shfl_down_sync(0xffffffffu, s, 4);
        s += __shfl_down_sync(0xffffffffu, s, 2);
        s += __shfl_down_sync(0xffffffffu, s, 1);
        if ((t & 7) == 0) atomicAdd(&g_Z[b * Dd + d], s);
    }
    __syncthreads();

    {   // partial context[d][e] += sum_n W[d][n] * K[e][n]
        int d  = t >> 3;
        int e0 = (t & 7) * 4;
        float a0 = 0.f, a1 = 0.f, a2 = 0.f, a3 = 0.f;
#pragma unroll 4
        for (int n = 0; n < CH; n++) {
            float w = Ws[d * CHP + n];
            a0 += w * Ks[(e0 + 0) * CHP + n];
            a1 += w * Ks[(e0 + 1) * CHP + n];
            a2 += w * Ks[(e0 + 2) * CHP + n];
            a3 += w * Ks[(e0 + 3) * CHP + n];
        }
        float* cp = &g_ctx[((size_t)b * Dd + d) * Dd + e0];
        atomicAdd(cp + 0, a0); atomicAdd(cp + 1, a1);
        atomicAdd(cp + 2, a2); atomicAdd(cp + 3, a3);
    }
}

// ======================= kernel D: normalize context ========================
__global__ void ctxnorm_kernel()
{
    int i = blockIdx.x * 256 + threadIdx.x;
    if (i < Bn * Dd * Dd) g_ctxn[i] = g_ctx[i] / g_Z[i / Dd];
}

// ======================= main fused kernel ===================================
#define TN 64
#define KT 16

// Streamed 256x256 (A, global, row-major) @ 256xTN (B, smem) -> 8x8/thread in f32x2.
__device__ __forceinline__ void gemm_tile(
    const float* __restrict__ A, const float* __restrict__ Xs, float* __restrict__ As,
    int t, int tr, int tc, unsigned long long C2[8][4])
{
#pragma unroll
    for (int i = 0; i < 8; i++)
#pragma unroll
        for (int j = 0; j < 4; j++) C2[i][j] = 0ull;

    {   // preload k-tile 0 transposed: As[0][k][m] = A[m][k]
        const float4* ap = (const float4*)(A + (size_t)t * 256);
        float4 r0 = ap[0], r1 = ap[1], r2 = ap[2], r3 = ap[3];
        As[ 0*256 + t] = r0.x; As[ 1*256 + t] = r0.y; As[ 2*256 + t] = r0.z; As[ 3*256 + t] = r0.w;
        As[ 4*256 + t] = r1.x; As[ 5*256 + t] = r1.y; As[ 6*256 + t] = r1.z; As[ 7*256 + t] = r1.w;
        As[ 8*256 + t] = r2.x; As[ 9*256 + t] = r2.y; As[10*256 + t] = r2.z; As[11*256 + t] = r2.w;
        As[12*256 + t] = r3.x; As[13*256 + t] = r3.y; As[14*256 + t] = r3.z; As[15*256 + t] = r3.w;
    }
    __syncthreads();

#pragma unroll 1
    for (int kt = 0; kt < 16; kt++) {
        float4 p0, p1, p2, p3;
        if (kt < 15) {   // prefetch next A tile into registers
            const float4* ap = (const float4*)(A + (size_t)t * 256 + (kt + 1) * KT);
            p0 = ap[0]; p1 = ap[1]; p2 = ap[2]; p3 = ap[3];
        }
        const float* Ac = As + (kt & 1) * (KT * 256);
        const float* Bc = Xs + kt * (KT * TN);
#pragma unroll
        for (int k = 0; k < KT; k++) {
            float4 a0 = *(const float4*)(Ac + k * 256 + tr * 8);
            float4 a1 = *(const float4*)(Ac + k * 256 + tr * 8 + 4);
            float4 b0 = *(const float4*)(Bc + k * TN + tc * 8);
            float4 b1 = *(const float4*)(Bc + k * TN + tc * 8 + 4);
            unsigned long long bb0 = pk2(b0.x, b0.y);
            unsigned long long bb1 = pk2(b0.z, b0.w);
            unsigned long long bb2 = pk2(b1.x, b1.y);
            unsigned long long bb3 = pk2(b1.z, b1.w);
            float av[8] = {a0.x, a0.y, a0.z, a0.w, a1.x, a1.y, a1.z, a1.w};
#pragma unroll
            for (int i = 0; i < 8; i++) {
                unsigned long long aa = pk2(av[i], av[i]);
                fma2(C2[i][0], aa, bb0);
                fma2(C2[i][1], aa, bb1);
                fma2(C2[i][2], aa, bb2);
                fma2(C2[i][3], aa, bb3);
            }
        }
        if (kt < 15) {
            float* dst = As + ((kt + 1) & 1) * (KT * 256);
            dst[ 0*256 + t] = p0.x; dst[ 1*256 + t] = p0.y; dst[ 2*256 + t] = p0.z; dst[ 3*256 + t] = p0.w;
            dst[ 4*256 + t] = p1.x; dst[ 5*256 + t] = p1.y; dst[ 6*256 + t] = p1.z; dst[ 7*256 + t] = p1.w;
            dst[ 8*256 + t] = p2.x; dst[ 9*256 + t] = p2.y; dst[10*256 + t] = p2.z; dst[11*256 + t] = p2.w;
            dst[12*256 + t] = p3.x; dst[13*256 + t] = p3.y; dst[14*256 + t] = p3.z; dst[15*256 + t] = p3.w;
            __syncthreads();
        }
    }
    __syncthreads();
}

__global__ void __launch_bounds__(256, 2)
main_kernel(const float* __restrict__ x,
            const float* __restrict__ wq, const float* __restrict__ qsc, const float* __restrict__ qbi,
            const float* __restrict__ wp, const float* __restrict__ psc, const float* __restrict__ pbi,
            float* __restrict__ out)
{
    extern __shared__ float sh[];
    float* Xs = sh;                        // [256][64] : x -> qsm -> att -> out
    float* As = sh + 256 * TN;             // [2][16][256] streamed weight tiles
    float* Cx = sh + 256 * TN + 2 * KT * 256;  // [32][32] normalized context

    const int b  = blockIdx.y;
    const int n0 = blockIdx.x * TN;
    const int t  = threadIdx.x;
    const int tc = t & 7;
    const int tr = t >> 3;

    {   // coalesced float4 load of x tile [256][64]
        const float4* xp = (const float4*)(x + (size_t)b * Cdim * Nsp + n0);
#pragma unroll
        for (int it = 0; it < 16; it++) {
            int f  = it * 256 + t;     // 0..4095 ; row = f/16, col4 = f%16
            int c  = f >> 4;
            int n4 = f & 15;
            ((float4*)Xs)[f] = xp[(size_t)c * (Nsp / 4) + n4];
        }
    }
    ((float4*)Cx)[t & 255] = ((const float4*)(g_ctxn + (size_t)b * Dd * Dd))[t];
    __syncthreads();

    unsigned long long C2[8][4];

    // ---- GEMM1: q = wq @ x ----
    gemm_tile(wq, Xs, As, t, tr, tc, C2);

    // q affine -> Xs (overwrites x tile)
#pragma unroll
    for (int i = 0; i < 8; i++) {
        int m = tr * 8 + i;
        float s = __ldg(qsc + m), bia = __ldg(qbi + m);
#pragma unroll
        for (int j = 0; j < 4; j++) {
            float f0, f1; upk2(C2[i][j], f0, f1);
            Xs[m * TN + tc * 8 + 2 * j]     = f0 * s + bia;
            Xs[m * TN + tc * 8 + 2 * j + 1] = f1 * s + bia;
        }
    }
    __syncthreads();

    // ---- softmax over D per (head, column) ----
#pragma unroll
    for (int gg = 0; gg < 2; gg++) {
        int g   = t + gg * 256;     // 512 groups = 8 heads x 64 cols
        int col = g & 63;
        int h   = g >> 6;
        float* base = Xs + (h * Dd) * TN + col;
        float mx = base[0];
#pragma unroll
        for (int d = 1; d < Dd; d++) mx = fmaxf(mx, base[d * TN]);
        float ev[Dd];
        float sum = 0.f;
#pragma unroll
        for (int d = 0; d < Dd; d++) { ev[d] = __expf(base[d * TN] - mx); sum += ev[d]; }
        float inv = 1.f / sum;
#pragma unroll
        for (int d = 0; d < Dd; d++) base[d * TN] = ev[d] * inv;
    }
    __syncthreads();

    // ---- attended = ctx^T @ qsm per head, then ReLU, back into Xs ----
    float Areg[8][8];
#pragma unroll
    for (int i = 0; i < 8; i++)
#pragma unroll
        for (int j = 0; j < 8; j++) Areg[i][j] = 0.f;
    {
        int h  = tr >> 2;            // rows tr*8..tr*8+7 all live in head h
        int e0 = (tr & 3) * 8;       // h*32+e0 == tr*8
#pragma unroll
        for (int d = 0; d < Dd; d++) {
            const float* qrow = Xs + (h * Dd + d) * TN + tc * 8;
            float4 q0 = *(const float4*)qrow;
            float4 q1 = *(const float4*)(qrow + 4);
            const float* crow = Cx + d * Dd + e0;
            float4 c0 = *(const float4*)crow;
            float4 c1 = *(const float4*)(crow + 4);
            float qv[8] = {q0.x, q0.y, q0.z, q0.w, q1.x, q1.y, q1.z, q1.w};
            float cv[8] = {c0.x, c0.y, c0.z, c0.w, c1.x, c1.y, c1.z, c1.w};
#pragma unroll
            for (int i = 0; i < 8; i++)
#pragma unroll
                for (int j = 0; j < 8; j++) Areg[i][j] += cv[i] * qv[j];
        }
    }
    __syncthreads();
#pragma unroll
    for (int i = 0; i < 8; i++)
#pragma unroll
        for (int j = 0; j < 8; j++)
            Xs[(tr * 8 + i) * TN + tc * 8 + j] = fmaxf(Areg[i][j], 0.f);
    __syncthreads();

    // ---- GEMM2: out = wp @ relu(att) ----
    gemm_tile(wp, Xs, As, t, tr, tc, C2);

    // p affine -> Xs, then coalesced store
#pragma unroll
    for (int i = 0; i < 8; i++) {
        int m = tr * 8 + i;
        float s = __ldg(psc + m), bia = __ldg(pbi + m);
#pragma unroll
        for (int j = 0; j < 4; j++) {
            float f0, f1; upk2(C2[i][j], f0, f1);
            Xs[m * TN + tc * 8 + 2 * j]     = f0 * s + bia;
            Xs[m * TN + tc * 8 + 2 * j + 1] = f1 * s + bia;
        }
    }
    __syncthreads();
    {
        float4* op = (float4*)(out + (size_t)b * Cdim * Nsp + n0);
#pragma unroll
        for (int it = 0; it < 16; it++) {
            int f  = it * 256 + t;
            int c  = f >> 4;
            int n4 = f & 15;
            op[(size_t)c * (Nsp / 4) + n4] = ((float4*)Xs)[f];
        }
    }
}

// ======================= launch =============================================
extern "C" void kernel_launch(void* const* d_in, const int* in_sizes, int n_in,
                              void* d_out, int out_size)
{
    const float* x   = (const float*)d_in[0];
    const float* wq  = (const float*)d_in[1];
    const float* qsc = (const float*)d_in[2];
    const float* qbi = (const float*)d_in[3];
    const float* wkv = (const float*)d_in[4];
    const float* kvs = (const float*)d_in[5];
    const float* kvb = (const float*)d_in[6];
    const float* wp  = (const float*)d_in[7];
    const float* psc = (const float*)d_in[8];
    const float* pbi = (const float*)d_in[9];
    float* out = (float*)d_out;

    const int CTX_SMEM  = 2 * Dd * CHP * (int)sizeof(float);                 // 65792
    const int MAIN_SMEM = (256 * TN + 2 * KT * 256 + Dd * Dd) * (int)sizeof(float); // 102400

    cudaFuncSetAttribute(ctx_kernel,  cudaFuncAttributeMaxDynamicSharedMemorySize, CTX_SMEM);
    cudaFuncSetAttribute(main_kernel, cudaFuncAttributeMaxDynamicSharedMemorySize, MAIN_SMEM);

    kv_kernel<<<dim3(Nsp / 256, Bn), 256>>>(x, wkv, kvs, kvb);
    rowmax_kernel<<<Bn * Dd, 256>>>();
    zero_kernel<<<(Bn * Dd * Dd + 255) / 256, 256>>>();
    ctx_kernel<<<dim3(Nsp / CH, Bn), 256, CTX_SMEM>>>();
    ctxnorm_kernel<<<(Bn * Dd * Dd + 255) / 256, 256>>>();
    main_kernel<<<dim3(Nsp / TN, Bn), 256, MAIN_SMEM>>>(x, wq, qsc, qbi, wp, psc, pbi, out);
}